// round 8
// baseline (speedup 1.0000x reference)
#include <cuda_runtime.h>
#include <math.h>
#include <stdint.h>

#define AA 3072   // A = BS * IA
#define DD 2048   // D = BS * (IA-1)
#define NB 1024   // BS

// scratch ping-pong buffers (no device allocation allowed)
__device__ float g_buf0[AA];
__device__ float g_buf1[AA];

__device__ __forceinline__ void l2_prefetch(const void* p, uint32_t bytes) {
    asm volatile("cp.async.bulk.prefetch.L2.global [%0], %1;"
                 :: "l"(p), "r"(bytes) : "memory");
}

// ---------------------------------------------------------------------------
// bootstrap: prefetch first weight matrix into L2 (fire-and-forget)
// grid*block threads each prefetch one 32 KB chunk
// ---------------------------------------------------------------------------
__global__ void prefetch_kernel(const float* __restrict__ W, int total_bytes) {
    int idx = blockIdx.x * blockDim.x + threadIdx.x;
    int off = idx * 32768;
    if (off < total_bytes)
        l2_prefetch((const char*)W + off, 32768);
}

// ---------------------------------------------------------------------------
// GEMV, warp-per-row, deep explicit load pipeline (8 LDG.128 in flight,
// double-buffered), plus fire-and-forget L2 prefetch of the NEXT layer's
// weight slice. ACT: 0 none, 1 tanh, 2 tanhshrink.
// ---------------------------------------------------------------------------
template<int ACT, int COLS>
__global__ void __launch_bounds__(256, 2)
gemv_ws(const float* __restrict__ W, const float* __restrict__ x,
        const float* __restrict__ b, float* __restrict__ y,
        const char* __restrict__ nextW, unsigned chunk_bytes)
{
    constexpr int F4       = COLS / 4;     // 768 or 512 float4 per row
    constexpr int PER_LANE = F4 / 32;      // 24 or 16
    constexpr int NBATCH   = PER_LANE / 8; // 3 or 2

    __shared__ float sx[COLS];

    const int lane = threadIdx.x & 31;
    const int warp = threadIdx.x >> 5;
    const int row  = blockIdx.x * 8 + warp;

    // prefetch next layer's weight slice for this block (warp 0, fire & forget)
    if (warp == 0 && nextW) {
        unsigned off = (unsigned)lane * 32768u;
        if (off < chunk_bytes)
            l2_prefetch(nextW + (size_t)blockIdx.x * chunk_bytes + off, 32768u);
    }

    const float4* __restrict__ W4 =
        reinterpret_cast<const float4*>(W + (size_t)row * COLS);

    // stage x into shared
    const float4* __restrict__ xg4 = reinterpret_cast<const float4*>(x);
    float4* sx4 = reinterpret_cast<float4*>(sx);
    #pragma unroll
    for (int k = 0; k < F4 / 256; ++k)
        sx4[threadIdx.x + 256 * k] = xg4[threadIdx.x + 256 * k];

    // prologue: batch 0 of W issued BEFORE the barrier
    float4 buf[2][8];
    #pragma unroll
    for (int t = 0; t < 8; ++t)
        buf[0][t] = __ldcs(&W4[lane + 32 * t]);

    __syncthreads();

    float a0 = 0.f, a1 = 0.f, a2 = 0.f, a3 = 0.f;
    #pragma unroll
    for (int bt = 0; bt < NBATCH; ++bt) {
        const int cur = bt & 1;
        if (bt + 1 < NBATCH) {
            #pragma unroll
            for (int t = 0; t < 8; ++t)
                buf[cur ^ 1][t] = __ldcs(&W4[lane + 32 * (8 * (bt + 1) + t)]);
        }
        #pragma unroll
        for (int t = 0; t < 8; ++t) {
            float4 v = sx4[lane + 32 * (8 * bt + t)];
            a0 = fmaf(buf[cur][t].x, v.x, a0);
            a1 = fmaf(buf[cur][t].y, v.y, a1);
            a2 = fmaf(buf[cur][t].z, v.z, a2);
            a3 = fmaf(buf[cur][t].w, v.w, a3);
        }
    }
    float acc = (a0 + a1) + (a2 + a3);

    #pragma unroll
    for (int off = 16; off; off >>= 1)
        acc += __shfl_xor_sync(0xFFFFFFFFu, acc, off);

    if (lane == 0) {
        float h = acc + b[row];
        if (ACT == 1)      h = tanhf(h);
        else if (ACT == 2) h = h - tanhf(h);
        y[row] = h;
    }
}

// ---------------------------------------------------------------------------
// pdist: out[i*1024 + j] = || a[i,:] - a[j,:] ||_2   (a: [1024, DIMS])
// ---------------------------------------------------------------------------
template<int DIMS>
__global__ void __launch_bounds__(256) pdist_kernel(const float* __restrict__ a,
                                                    float* __restrict__ out)
{
    __shared__ float s[NB * DIMS];
    for (int t = threadIdx.x; t < NB * DIMS; t += 256) s[t] = a[t];
    __syncthreads();

    const int idx = blockIdx.x * 256 + threadIdx.x;   // 0 .. 1024*1024-1
    const int i = idx >> 10;
    const int j = idx & (NB - 1);

    float d2 = 0.f;
    #pragma unroll
    for (int k = 0; k < DIMS; ++k) {
        float d = s[i * DIMS + k] - s[j * DIMS + k];
        d2 = fmaf(d, d, d2);
    }
    out[idx] = sqrtf(d2);
}

// ---------------------------------------------------------------------------
// kernel_launch: bootstrap prefetch -> encoder -> pdists -> decoder, with
// each GEMV prefetching the next layer's W into L2 (software pipeline that
// keeps the DRAM stream continuous across the whole graph).
// output layout: [output(3072) | in_diff(1024^2) | lat_diff(1024^2) | lat_repr(2048)]
// ---------------------------------------------------------------------------
extern "C" void kernel_launch(void* const* d_in, const int* in_sizes, int n_in,
                              void* d_out, int out_size)
{
    (void)in_sizes; (void)n_in; (void)out_size;

    const float* x   = (const float*)d_in[0];
    const float* ew1 = (const float*)d_in[1];
    const float* eb1 = (const float*)d_in[2];
    const float* ew2 = (const float*)d_in[3];
    const float* eb2 = (const float*)d_in[4];
    const float* ew3 = (const float*)d_in[5];
    const float* eb3 = (const float*)d_in[6];
    const float* ew4 = (const float*)d_in[7];
    const float* eb4 = (const float*)d_in[8];
    const float* dw1 = (const float*)d_in[9];
    const float* db1 = (const float*)d_in[10];
    const float* dw2 = (const float*)d_in[11];
    const float* db2 = (const float*)d_in[12];
    const float* dw3 = (const float*)d_in[13];
    const float* db3 = (const float*)d_in[14];
    const float* dw4 = (const float*)d_in[15];
    const float* db4 = (const float*)d_in[16];

    float* out      = (float*)d_out;
    float* out_main = out;                          // 3072
    float* out_ind  = out + AA;                     // 1024*1024
    float* out_lat  = out + AA + NB * NB;           // 1024*1024
    float* y        = out + AA + 2 * NB * NB;       // 2048 (lat_repr / encoder out)

    float *buf0, *buf1;
    cudaGetSymbolAddress((void**)&buf0, g_buf0);
    cudaGetSymbolAddress((void**)&buf1, g_buf1);

    constexpr unsigned BYTES_AA = (unsigned)AA * AA * 4u;   // 37.75 MB
    constexpr unsigned BYTES_DA = (unsigned)DD * AA * 4u;   // 25.17 MB
    // per-block prefetch chunk sizes (all divide evenly into 3x/1x 32 KB):
    constexpr unsigned CH_AA_384 = BYTES_AA / (AA / 8);     // 98304 (3 x 32K)
    constexpr unsigned CH_DA_256 = BYTES_DA / (DD / 8);     // 98304
    constexpr unsigned CH_DA_384 = BYTES_DA / (AA / 8);     // 65536 (2 x 32K)
    constexpr unsigned CH_AA_256 = BYTES_AA / (DD / 8);     // 147456 -> cap at 4x32K? no: 4.5x32K
    // ew4 grid = 256 blocks prefetching dw1 (25.17 MB): 98304 each (3 x 32K)

    // bootstrap: get ew1 streaming into L2 immediately (fire-and-forget)
    prefetch_kernel<<<9, 128>>>(ew1, (int)BYTES_AA);

    // in_data pdist depends only on x
    pdist_kernel<3><<<(NB * NB) / 256, 256>>>(x, out_ind);

    // encoder: each layer prefetches the next layer's weights
    gemv_ws<1, AA><<<AA / 8, 256>>>(ew1, x,    eb1, buf0, (const char*)ew2, CH_AA_384);
    gemv_ws<1, AA><<<AA / 8, 256>>>(ew2, buf0, eb2, buf1, (const char*)ew3, CH_AA_384);
    gemv_ws<0, AA><<<AA / 8, 256>>>(ew3, buf1, eb3, buf0, (const char*)ew4, CH_DA_384);
    gemv_ws<2, AA><<<DD / 8, 256>>>(ew4, buf0, eb4, y,    (const char*)dw1, CH_DA_256);

    // latent pdist
    pdist_kernel<2><<<(NB * NB) / 256, 256>>>(y, out_lat);

    // decoder
    gemv_ws<1, DD><<<AA / 8, 256>>>(dw1, y,    db1, buf0, (const char*)dw2, CH_AA_384);
    gemv_ws<1, AA><<<AA / 8, 256>>>(dw2, buf0, db2, buf1, (const char*)dw3, CH_AA_384);
    gemv_ws<0, AA><<<AA / 8, 256>>>(dw3, buf1, db3, buf0, (const char*)dw4, CH_AA_384);
    gemv_ws<1, AA><<<AA / 8, 256>>>(dw4, buf0, db4, out_main, (const char*)0, 0u);
}

// round 9
// speedup vs baseline: 1.3330x; 1.3330x over previous
#include <cuda_runtime.h>
#include <math.h>
#include <stdint.h>

#define AA 3072          // A = BS * IA
#define DD 2048          // D = BS * (IA-1)
#define NB 1024          // BS
#define NBLK 296         // persistent grid: 2 CTAs/SM * 148 SMs (<= GB300 capacity)
#define NWARP (NBLK * 8) // 2368 global warps

__device__ float g_buf0[AA];
__device__ float g_buf1[AA];
__device__ unsigned g_bar;    // zero-init; reset at end of every run
__device__ unsigned g_exit;

__device__ __forceinline__ void l2_prefetch(const void* p, uint32_t bytes) {
    asm volatile("cp.async.bulk.prefetch.L2.global [%0], %1;"
                 :: "l"(p), "r"(bytes) : "memory");
}

// ---------------------------------------------------------------------------
// grid-wide barrier (all NBLK blocks resident -> spin is safe)
// ---------------------------------------------------------------------------
__device__ __forceinline__ void grid_bar(int tid, unsigned target) {
    __threadfence();          // make this thread's global stores visible
    __syncthreads();          // all block stores done
    if (tid == 0) {
        atomicAdd(&g_bar, 1u);
        while (*(volatile unsigned*)&g_bar < target) { }
        __threadfence();
    }
    __syncthreads();
}

// ---------------------------------------------------------------------------
// one row dot-product: deep double-buffered LDG.128 pipeline (8 in flight)
// ACT: 0 none, 1 tanh, 2 tanhshrink
// ---------------------------------------------------------------------------
template<int ACT, int COLS>
__device__ __forceinline__ void dot_row(const float* __restrict__ W,
                                        const float* __restrict__ sx,
                                        const float* __restrict__ b,
                                        float* __restrict__ y,
                                        int row, int lane)
{
    constexpr int NBATCH = COLS / 4 / 32 / 8;   // 3 (COLS=3072) or 2 (2048)
    const float4* __restrict__ W4 =
        reinterpret_cast<const float4*>(W + (size_t)row * COLS);
    const float4* __restrict__ sx4 = reinterpret_cast<const float4*>(sx);

    float4 buf[2][8];
    #pragma unroll
    for (int t = 0; t < 8; ++t)
        buf[0][t] = __ldcs(&W4[lane + 32 * t]);

    float a0 = 0.f, a1 = 0.f, a2 = 0.f, a3 = 0.f;
    #pragma unroll
    for (int bt = 0; bt < NBATCH; ++bt) {
        const int cur = bt & 1;
        if (bt + 1 < NBATCH) {
            #pragma unroll
            for (int t = 0; t < 8; ++t)
                buf[cur ^ 1][t] = __ldcs(&W4[lane + 32 * (8 * (bt + 1) + t)]);
        }
        #pragma unroll
        for (int t = 0; t < 8; ++t) {
            float4 v = sx4[lane + 32 * (8 * bt + t)];
            a0 = fmaf(buf[cur][t].x, v.x, a0);
            a1 = fmaf(buf[cur][t].y, v.y, a1);
            a2 = fmaf(buf[cur][t].z, v.z, a2);
            a3 = fmaf(buf[cur][t].w, v.w, a3);
        }
    }
    float acc = (a0 + a1) + (a2 + a3);
    #pragma unroll
    for (int off = 16; off; off >>= 1)
        acc += __shfl_xor_sync(0xFFFFFFFFu, acc, off);

    if (lane == 0) {
        float h = acc + b[row];
        if (ACT == 1)      h = tanhf(h);
        else if (ACT == 2) h = h - tanhf(h);
        y[row] = h;
    }
}

// stage x into smem then compute this warp's rows
template<int ACT, int COLS, int ROWS>
__device__ __forceinline__ void layer(const float* __restrict__ W,
                                      const float* __restrict__ xg,
                                      const float* __restrict__ b,
                                      float* __restrict__ y,
                                      float* sx, int tid, int gw, int lane)
{
    const float4* __restrict__ xg4 = reinterpret_cast<const float4*>(xg);
    float4* sx4 = reinterpret_cast<float4*>(sx);
    for (int k = tid; k < COLS / 4; k += 256) sx4[k] = __ldg(&xg4[k]);
    __syncthreads();
    for (int row = gw; row < ROWS; row += NWARP)
        dot_row<ACT, COLS>(W, sx, b, y, row, lane);
}

// fire-and-forget L2 prefetch of this warp's rows of the NEXT weight matrix
__device__ __forceinline__ void prefetch_rows(const float* W, int rows, int cols,
                                              int gw, int lane)
{
    if (lane == 0)
        for (int r = gw; r < rows; r += NWARP)
            l2_prefetch(W + (size_t)r * cols, (uint32_t)(cols * 4));
}

// pdist chunk: out[i*1024+j] = ||a[i]-a[j]||
template<int DIMS>
__device__ __forceinline__ void pdist_fused(const float* __restrict__ a,
                                            float* __restrict__ outp,
                                            float* s, int tid, int bid)
{
    __syncthreads();   // sx no longer in use
    for (int t = tid; t < NB * DIMS; t += 256) s[t] = a[t];
    __syncthreads();
    for (int idx = bid * 256 + tid; idx < NB * NB; idx += NBLK * 256) {
        const int i = idx >> 10;
        const int j = idx & (NB - 1);
        float d2 = 0.f;
        #pragma unroll
        for (int k = 0; k < DIMS; ++k) {
            float d = s[i * DIMS + k] - s[j * DIMS + k];
            d2 = fmaf(d, d, d2);
        }
        outp[idx] = sqrtf(d2);
    }
}

// ---------------------------------------------------------------------------
// the whole network in one persistent kernel
// ---------------------------------------------------------------------------
__global__ void __launch_bounds__(256, 2)
fused_net(const float* __restrict__ x,
          const float* __restrict__ ew1, const float* __restrict__ eb1,
          const float* __restrict__ ew2, const float* __restrict__ eb2,
          const float* __restrict__ ew3, const float* __restrict__ eb3,
          const float* __restrict__ ew4, const float* __restrict__ eb4,
          const float* __restrict__ dw1, const float* __restrict__ db1,
          const float* __restrict__ dw2, const float* __restrict__ db2,
          const float* __restrict__ dw3, const float* __restrict__ db3,
          const float* __restrict__ dw4, const float* __restrict__ db4,
          float* __restrict__ out)
{
    __shared__ float sx[AA];    // 12 KB: layer input / pdist points

    const int tid  = threadIdx.x;
    const int bid  = blockIdx.x;
    const int lane = tid & 31;
    const int gw   = bid * 8 + (tid >> 5);

    float* out_main = out;                      // 3072
    float* out_ind  = out + AA;                 // 1024*1024
    float* out_lat  = out + AA + NB * NB;       // 1024*1024
    float* y        = out + AA + 2 * NB * NB;   // 2048 (lat_repr)

    // L1: x -> buf0 (tanh); prefetch ew2 during tail/spin
    layer<1, AA, AA>(ew1, x, eb1, g_buf0, sx, tid, gw, lane);
    prefetch_rows(ew2, AA, AA, gw, lane);
    grid_bar(tid, NBLK * 1);

    // L2: buf0 -> buf1 (tanh); prefetch ew3
    layer<1, AA, AA>(ew2, g_buf0, eb2, g_buf1, sx, tid, gw, lane);
    prefetch_rows(ew3, AA, AA, gw, lane);
    grid_bar(tid, NBLK * 2);

    // L3: buf1 -> buf0 (none); prefetch ew4
    layer<0, AA, AA>(ew3, g_buf1, eb3, g_buf0, sx, tid, gw, lane);
    prefetch_rows(ew4, DD, AA, gw, lane);
    grid_bar(tid, NBLK * 3);

    // L4: buf0 -> y (tanhshrink, 2048 rows); prefetch dw1
    layer<2, AA, DD>(ew4, g_buf0, eb4, y, sx, tid, gw, lane);
    prefetch_rows(dw1, AA, DD, gw, lane);
    grid_bar(tid, NBLK * 4);

    // L5: y -> buf0 (tanh, COLS=2048); prefetch dw2
    layer<1, DD, AA>(dw1, y, db1, g_buf0, sx, tid, gw, lane);
    prefetch_rows(dw2, AA, AA, gw, lane);
    grid_bar(tid, NBLK * 5);

    // L6: buf0 -> buf1 (tanh); prefetch dw3
    layer<1, AA, AA>(dw2, g_buf0, db2, g_buf1, sx, tid, gw, lane);
    prefetch_rows(dw3, AA, AA, gw, lane);
    grid_bar(tid, NBLK * 6);

    // L7: buf1 -> buf0 (none); prefetch dw4
    layer<0, AA, AA>(dw3, g_buf1, db3, g_buf0, sx, tid, gw, lane);
    prefetch_rows(dw4, AA, AA, gw, lane);
    grid_bar(tid, NBLK * 7);

    // L8: buf0 -> out_main (tanh)
    layer<1, AA, AA>(dw4, g_buf0, db4, out_main, sx, tid, gw, lane);

    // prefetch ew1 for the NEXT graph replay (fire & forget)
    prefetch_rows(ew1, AA, AA, gw, lane);

    // pdists (x and y both stable and globally visible via barriers 4..7)
    pdist_fused<3>(x, out_ind, sx, tid, bid);
    pdist_fused<2>(y, out_lat, sx, tid, bid);

    // exit: last block to finish resets the barrier counters for next replay
    __syncthreads();
    if (tid == 0) {
        unsigned done = atomicAdd(&g_exit, 1u);
        if (done == NBLK - 1) {
            g_bar  = 0;
            g_exit = 0;
            __threadfence();
        }
    }
}

// ---------------------------------------------------------------------------
extern "C" void kernel_launch(void* const* d_in, const int* in_sizes, int n_in,
                              void* d_out, int out_size)
{
    (void)in_sizes; (void)n_in; (void)out_size;

    fused_net<<<NBLK, 256>>>(
        (const float*)d_in[0],
        (const float*)d_in[1],  (const float*)d_in[2],
        (const float*)d_in[3],  (const float*)d_in[4],
        (const float*)d_in[5],  (const float*)d_in[6],
        (const float*)d_in[7],  (const float*)d_in[8],
        (const float*)d_in[9],  (const float*)d_in[10],
        (const float*)d_in[11], (const float*)d_in[12],
        (const float*)d_in[13], (const float*)d_in[14],
        (const float*)d_in[15], (const float*)d_in[16],
        (float*)d_out);
}